// round 2
// baseline (speedup 1.0000x reference)
#include <cuda_runtime.h>

#define NBINS 8192
#define N_LEV 1024
#define XMIN_F (-4.25f)
#define XMAX_F (4.25f)

__device__ float    g_grid[N_LEV];
__device__ float    g_lut[N_LEV];
__device__ unsigned g_bins[NBINS];

// ---------------------------------------------------------------------------
// Exact reference nearest-index against a grid array (searchsorted 'left'
// then abs-distance compare, exactly matching the reference tie-break).
// ---------------------------------------------------------------------------
__device__ __forceinline__ int nidx_exact_s(float x, const float* __restrict__ grid)
{
    int l = 0, r = N_LEV;                 // first i with grid[i] >= x
    while (l < r) {
        int m = (l + r) >> 1;
        if (grid[m] < x) l = m + 1; else r = m;
    }
    int idx = l < 1 ? 1 : (l > N_LEV - 1 ? N_LEV - 1 : l);
    float left  = grid[idx - 1];
    float right = grid[idx];
    return (fabsf(x - left) < fabsf(x - right)) ? idx - 1 : idx;
}

// ---------------------------------------------------------------------------
// Fused prep: one block, 1024 threads.
//  Phase 1: grid = h[:,0]; lut[i] = sum_t (h-chain step >= T[t]) * d[t] - b
//  Phase 2: 8 bins per thread, binary searches against SMEM grid.
// Widened bin edges (±0.25*W, far above fp rounding of the bin quantizer)
// guarantee lo <= nidx(x) <= hi for every x that maps to bin j.
// Unambiguous bin -> final output float. Ambiguous -> (lo,hi) packed into
// negative-NaN space (0xFFC00000+) which no legitimate output can hit.
// ---------------------------------------------------------------------------
__global__ void prep_all(const float* __restrict__ h,
                         const float* __restrict__ d,
                         const float* __restrict__ T,
                         const float* __restrict__ b)
{
    __shared__ float s_grid[N_LEV];
    __shared__ float s_lut[N_LEV];

    int i = threadIdx.x;
    float v = h[i * 9 + 0];
    s_grid[i] = v;
    g_grid[i] = v;
    float out = 0.0f;
#pragma unroll
    for (int t = 1; t <= 8; ++t) {
        if (v - T[t] >= 0.0f) out += d[t];
        if (t != 8) v = h[i * 9 + t + 1];
    }
    out -= b[0];
    s_lut[i] = out;
    g_lut[i] = out;
    __syncthreads();

    const float W = (XMAX_F - XMIN_F) / (float)NBINS;
#pragma unroll
    for (int k = 0; k < NBINS / N_LEV; ++k) {
        int j = i + k * N_LEV;
        float eL = XMIN_F + (float)j       * W - 0.25f * W;
        float eR = XMIN_F + (float)(j + 1) * W + 0.25f * W;
        int lo = nidx_exact_s(eL, s_grid);
        int hi = nidx_exact_s(eR, s_grid);
        g_bins[j] = (lo == hi) ? __float_as_uint(s_lut[lo])
                               : (0xFFC00000u | ((unsigned)lo << 10) | (unsigned)hi);
    }
}

// ---------------------------------------------------------------------------
// Main kernel
// ---------------------------------------------------------------------------
__device__ __forceinline__ float eval_one(float x,
                                          const unsigned* __restrict__ s_bins,
                                          const float* __restrict__ s_grid,
                                          const float* __restrict__ s_lut)
{
    const float scale = (float)NBINS / (XMAX_F - XMIN_F);
    float t = (x - XMIN_F) * scale;
    int j = (int)t;
    j = j < 0 ? 0 : (j > NBINS - 1 ? NBINS - 1 : j);
    unsigned u = s_bins[j];
    if (u < 0xFFC00000u) return __uint_as_float(u);    // fast path (~80%)
    int nidx = (int)((u >> 10) & 1023u);
    int hi   = (int)(u & 1023u);
    float gl = s_grid[nidx];
    while (nidx < hi) {                                 // usually 1 iter
        float gr = s_grid[nidx + 1];
        if (fabsf(x - gl) < fabsf(x - gr)) break;       // exact ref tie-break
        ++nidx; gl = gr;
    }
    return s_lut[nidx];
}

__global__ void __launch_bounds__(256, 5)
ps_act_main(const float4* __restrict__ xin, float4* __restrict__ oout,
            int n4, const float* __restrict__ xs, float* __restrict__ os, int n)
{
    __shared__ unsigned s_bins[NBINS];
    __shared__ float    s_grid[N_LEV];
    __shared__ float    s_lut[N_LEV];

    for (int i = threadIdx.x; i < NBINS; i += blockDim.x) s_bins[i] = g_bins[i];
    for (int i = threadIdx.x; i < N_LEV; i += blockDim.x) {
        s_grid[i] = g_grid[i];
        s_lut[i]  = g_lut[i];
    }
    __syncthreads();

    int tid     = blockIdx.x * blockDim.x + threadIdx.x;
    int nthread = gridDim.x * blockDim.x;

    // Grid-stride, unroll-2 at offsets (i, i+nthread): every LDG.128 is a
    // fully-coalesced 512B warp access (one L1 wavefront each).
    int i = tid;
    for (; i + nthread < n4; i += 2 * nthread) {
        float4 a = xin[i];
        float4 c = xin[i + nthread];
        float4 ra, rc;
        ra.x = eval_one(a.x, s_bins, s_grid, s_lut);
        ra.y = eval_one(a.y, s_bins, s_grid, s_lut);
        ra.z = eval_one(a.z, s_bins, s_grid, s_lut);
        ra.w = eval_one(a.w, s_bins, s_grid, s_lut);
        rc.x = eval_one(c.x, s_bins, s_grid, s_lut);
        rc.y = eval_one(c.y, s_bins, s_grid, s_lut);
        rc.z = eval_one(c.z, s_bins, s_grid, s_lut);
        rc.w = eval_one(c.w, s_bins, s_grid, s_lut);
        oout[i]           = ra;
        oout[i + nthread] = rc;
    }
    if (i < n4) {
        float4 a = xin[i];
        float4 ra;
        ra.x = eval_one(a.x, s_bins, s_grid, s_lut);
        ra.y = eval_one(a.y, s_bins, s_grid, s_lut);
        ra.z = eval_one(a.z, s_bins, s_grid, s_lut);
        ra.w = eval_one(a.w, s_bins, s_grid, s_lut);
        oout[i] = ra;
    }

    // scalar tail (n not divisible by 4) — empty for this shape
    for (int k = n4 * 4 + tid; k < n; k += nthread)
        os[k] = eval_one(xs[k], s_bins, s_grid, s_lut);
}

// ---------------------------------------------------------------------------
extern "C" void kernel_launch(void* const* d_in, const int* in_sizes, int n_in,
                              void* d_out, int out_size)
{
    const float* x = (const float*)d_in[0];
    const float* h = (const float*)d_in[1];
    const float* d = (const float*)d_in[2];
    const float* T = (const float*)d_in[3];
    const float* b = (const float*)d_in[4];
    float* out = (float*)d_out;
    int n  = in_sizes[0];
    int n4 = n >> 2;

    prep_all<<<1, 1024>>>(h, d, T, b);

    int blocks = 760;  // 5 CTAs/SM on 152 SMs, single wave
    ps_act_main<<<blocks, 256>>>((const float4*)x, (float4*)out, n4, x, out, n);
}